// round 1
// baseline (speedup 1.0000x reference)
#include <cuda_runtime.h>
#include <cuda_bf16.h>
#include <math_constants.h>

// ---------------- problem constants ----------------
#define CCH 512            // channels
#define HF 50
#define WF 75
#define NROI 512
#define FCIN 25088         // 512*7*7
#define FCD 4096
#define NLOC 84            // 21*4
#define NSC 21
#define NHEAD (NLOC + NSC) // 105

// ---------------- device scratch (no allocation allowed) ----------------
__device__ float g_pool[(size_t)NROI * FCIN];   // 51.4 MB
__device__ float g_fc1[(size_t)NROI * FCD];     // 8 MB
__device__ float g_fc2[(size_t)NROI * FCD];     // 8 MB

// ---------------- RoI adaptive max pool ----------------
// One block per roi; threads stride over channels; each thread computes the
// 7x7 adaptive-max bins for its channel. x is 7.7MB -> L2 resident.
__global__ void roi_pool_kernel(const float* __restrict__ x,
                                const float* __restrict__ rois,
                                float* __restrict__ pool)
{
    int n = blockIdx.x;
    __shared__ int rs[7], re[7], cs[7], ce[7];
    if (threadIdx.x == 0) {
        // rois * (1/16), truncation toward zero (values >= 0)
        int x1 = (int)(rois[n * 4 + 0] * 0.0625f);
        int y1 = (int)(rois[n * 4 + 1] * 0.0625f);
        int x2 = (int)(rois[n * 4 + 2] * 0.0625f);
        int y2 = (int)(rois[n * 4 + 3] * 0.0625f);
        int h = y2 - y1 + 1;
        int w = x2 - x1 + 1;
        #pragma unroll
        for (int p = 0; p < 7; p++) {
            rs[p] = y1 + (p * h) / 7;
            re[p] = y1 + ((p + 1) * h + 6) / 7;   // ceil
            cs[p] = x1 + (p * w) / 7;
            ce[p] = x1 + ((p + 1) * w + 6) / 7;
        }
    }
    __syncthreads();

    for (int c = threadIdx.x; c < CCH; c += blockDim.x) {
        const float* f = x + (size_t)c * HF * WF;
        float* out = pool + (size_t)n * FCIN + c * 49;
        #pragma unroll
        for (int ph = 0; ph < 7; ph++) {
            #pragma unroll
            for (int pw = 0; pw < 7; pw++) {
                float m = -CUDART_INF_F;
                for (int y = rs[ph]; y < re[ph]; y++) {
                    const float* frow = f + y * WF;
                    for (int xx = cs[pw]; xx < ce[pw]; xx++)
                        m = fmaxf(m, frow[xx]);
                }
                out[ph * 7 + pw] = m;
            }
        }
    }
}

// ---------------- tiled fp32 SGEMM + bias + optional ReLU ----------------
// C[M,N] = op(A[M,K] @ B[K,N] + bias[N]); A,B,C row-major.
// BM=128, BN=64, BK=16, 256 threads, per-thread 8x4 micro-tile.
#define BM 128
#define BN 64
#define BK 16

template <bool RELU>
__global__ __launch_bounds__(256, 2)
void sgemm_bias_kernel(int M, int N, int K,
                       const float* __restrict__ A,
                       const float* __restrict__ B,
                       const float* __restrict__ bias,
                       float* __restrict__ Cmat)
{
    __shared__ float As[BK][BM + 4];   // +4 pad: keeps 16B alignment, kills conflicts
    __shared__ float Bs[BK][BN];

    const int tid = threadIdx.x;
    const int tx = tid & 15;    // n dim (x4)
    const int ty = tid >> 4;    // m dim (x8)

    const float* Ablk = A + (size_t)blockIdx.y * BM * K;
    const float* Bblk = B + (size_t)blockIdx.x * BN;

    float acc[8][4];
    #pragma unroll
    for (int i = 0; i < 8; i++)
        #pragma unroll
        for (int j = 0; j < 4; j++) acc[i][j] = 0.f;

    for (int k0 = 0; k0 < K; k0 += BK) {
        // A tile: 128x16 floats = 512 float4, 2 per thread, store transposed
        #pragma unroll
        for (int t = 0; t < 2; t++) {
            int idx = tid + t * 256;
            int row = idx >> 2;
            int kc  = (idx & 3) * 4;
            float4 v = *(const float4*)(Ablk + (size_t)row * K + k0 + kc);
            As[kc + 0][row] = v.x;
            As[kc + 1][row] = v.y;
            As[kc + 2][row] = v.z;
            As[kc + 3][row] = v.w;
        }
        // B tile: 16x64 floats = 256 float4, 1 per thread
        {
            int row = tid >> 4;
            int n4  = (tid & 15) * 4;
            float4 v = *(const float4*)(Bblk + (size_t)(k0 + row) * N + n4);
            *(float4*)&Bs[row][n4] = v;
        }
        __syncthreads();

        #pragma unroll
        for (int k = 0; k < BK; k++) {
            float a[8], b[4];
            *(float4*)&a[0] = *(const float4*)&As[k][ty * 8 + 0];
            *(float4*)&a[4] = *(const float4*)&As[k][ty * 8 + 4];
            *(float4*)&b[0] = *(const float4*)&Bs[k][tx * 4];
            #pragma unroll
            for (int i = 0; i < 8; i++)
                #pragma unroll
                for (int j = 0; j < 4; j++)
                    acc[i][j] = fmaf(a[i], b[j], acc[i][j]);
        }
        __syncthreads();
    }

    // epilogue
    #pragma unroll
    for (int i = 0; i < 8; i++) {
        int m = blockIdx.y * BM + ty * 8 + i;
        #pragma unroll
        for (int j = 0; j < 4; j++) {
            int n = blockIdx.x * BN + tx * 4 + j;
            float v = acc[i][j] + bias[n];
            if (RELU) v = fmaxf(v, 0.f);
            Cmat[(size_t)m * N + n] = v;
        }
    }
}

// ---------------- final heads: locs [512,84], scores [512,21] ----------------
// 2 rois per block; fc rows cached in smem; threads o=0..104 read W columns
// coalesced (contiguous in o). W_loc+W_score (1.7MB) stay L2 resident.
__global__ __launch_bounds__(256)
void head_kernel(const float* __restrict__ fc,
                 const float* __restrict__ Wl, const float* __restrict__ bl,
                 const float* __restrict__ Ws, const float* __restrict__ bs,
                 float* __restrict__ out_loc, float* __restrict__ out_sc)
{
    __shared__ float s_fc[2][FCD];
    int n0 = blockIdx.x * 2;
    int tid = threadIdx.x;

    #pragma unroll
    for (int r = 0; r < 2; r++)
        for (int k = tid; k < FCD; k += 256)
            s_fc[r][k] = fc[(size_t)(n0 + r) * FCD + k];
    __syncthreads();

    int r = tid >> 7;          // 0 or 1
    int o = tid & 127;         // 0..127
    if (o < NHEAD) {
        const float* s = s_fc[r];
        float acc = 0.f;
        if (o < NLOC) {
            const float* w = Wl + o;
            #pragma unroll 4
            for (int k = 0; k < FCD; k++)
                acc = fmaf(s[k], w[(size_t)k * NLOC], acc);
            out_loc[(size_t)(n0 + r) * NLOC + o] = acc + bl[o];
        } else {
            int oo = o - NLOC;
            const float* w = Ws + oo;
            #pragma unroll 4
            for (int k = 0; k < FCD; k++)
                acc = fmaf(s[k], w[(size_t)k * NSC], acc);
            out_sc[(size_t)(n0 + r) * NSC + oo] = acc + bs[oo];
        }
    }
}

// ---------------- launch ----------------
extern "C" void kernel_launch(void* const* d_in, const int* in_sizes, int n_in,
                              void* d_out, int out_size)
{
    const float* x      = (const float*)d_in[0];
    const float* rois   = (const float*)d_in[1];
    const float* W1     = (const float*)d_in[2];
    const float* b1     = (const float*)d_in[3];
    const float* W2     = (const float*)d_in[4];
    const float* b2     = (const float*)d_in[5];
    const float* W_loc  = (const float*)d_in[6];
    const float* b_loc  = (const float*)d_in[7];
    const float* W_sc   = (const float*)d_in[8];
    const float* b_sc   = (const float*)d_in[9];
    float* out = (float*)d_out;

    float *p_pool, *p_fc1, *p_fc2;
    cudaGetSymbolAddress((void**)&p_pool, g_pool);
    cudaGetSymbolAddress((void**)&p_fc1,  g_fc1);
    cudaGetSymbolAddress((void**)&p_fc2,  g_fc2);

    // 1) RoI adaptive max pool -> g_pool [512, 25088]
    roi_pool_kernel<<<NROI, 256>>>(x, rois, p_pool);

    // 2) fc1 = relu(pool @ W1 + b1)   M=512 K=25088 N=4096
    dim3 g1(FCD / BN, NROI / BM);
    sgemm_bias_kernel<true><<<g1, 256>>>(NROI, FCD, FCIN, p_pool, W1, b1, p_fc1);

    // 3) fc2 = relu(fc1 @ W2 + b2)    M=512 K=4096 N=4096
    sgemm_bias_kernel<true><<<g1, 256>>>(NROI, FCD, FCD, p_fc1, W2, b2, p_fc2);

    // 4) heads -> d_out: [512*84] locs then [512*21] scores
    head_kernel<<<NROI / 2, 256>>>(p_fc2, W_loc, b_loc, W_sc, b_sc,
                                   out, out + (size_t)NROI * NLOC);
}

// round 4
// speedup vs baseline: 3.4530x; 3.4530x over previous
#include <cuda_runtime.h>
#include <cstdint>
#include <math_constants.h>

// ---------------- problem constants ----------------
#define CCH 512
#define HF 50
#define WF 75
#define NROI 512
#define FCIN 25088
#define FCD 4096
#define GN 4096
#define NLOC 84
#define NSC 21
#define NHEAD 105

// tcgen05 only exists in the sm_103a-specific compilation pass
#if defined(__CUDA_ARCH__) && defined(__CUDA_ARCH_FEAT_SM103_ALL)
#define HAS_TCGEN05 1
#else
#define HAS_TCGEN05 0
#endif

// ---------------- device scratch ----------------
__device__ float g_pool[(size_t)NROI * FCIN];    // 51.4 MB (tf32-rounded)
__device__ float g_fc1[(size_t)NROI * FCD];      // 8 MB (tf32-rounded)
__device__ float g_fc2[(size_t)NROI * FCD];      // 8 MB (full fp32)
__device__ float g_w1t[(size_t)FCIN * FCD];      // 411 MB W1^T [N,K], tf32-rounded
__device__ float g_w2t[(size_t)FCD * FCD];       // 67 MB  W2^T [N,K], tf32-rounded
__device__ float g_wt[(size_t)NHEAD * FCD];      // 1.7 MB transposed head weights

// ---------------- common helpers ----------------
__device__ __forceinline__ float tf32_rn(float x) {
    float r;
    asm("cvt.rna.tf32.f32 %0, %1;" : "=f"(r) : "f"(x));
    return r;
}
__device__ __forceinline__ uint32_t smem_u32(const void* p) {
    uint32_t a;
    asm("{ .reg .u64 t; cvta.to.shared.u64 t, %1; cvt.u32.u64 %0, t; }" : "=r"(a) : "l"(p));
    return a;
}
__device__ __forceinline__ void cpasync16(uint32_t dst, const void* src) {
    asm volatile("cp.async.cg.shared.global [%0], [%1], 16;" :: "r"(dst), "l"(src));
}
#define CP_COMMIT() asm volatile("cp.async.commit_group;" ::: "memory")
#define CP_WAIT3()  asm volatile("cp.async.wait_group 3;" ::: "memory")
#define SWZ(x) ((x) ^ (((x) >> 3) & 0x70))

#if HAS_TCGEN05
// ---------------- tcgen05 helpers (sm_103a pass only) ----------------
__device__ __forceinline__ void mbar_init(uint32_t mbar, uint32_t cnt) {
    asm volatile("mbarrier.init.shared.b64 [%0], %1;" :: "r"(mbar), "r"(cnt) : "memory");
}
__device__ __forceinline__ void mbar_wait(uint32_t mbar, uint32_t parity) {
    asm volatile(
        "{\n\t.reg .pred P;\n"
        "LW_%=:\n\t"
        "mbarrier.try_wait.parity.acquire.cta.shared::cta.b64 P, [%0], %1, 0x989680;\n\t"
        "@P bra.uni LD_%=;\n\t"
        "bra.uni LW_%=;\n"
        "LD_%=:\n\t}"
        :: "r"(mbar), "r"(parity) : "memory");
}
__device__ __forceinline__ void tmem_alloc(uint32_t smem_dst, uint32_t ncols) {
    asm volatile("tcgen05.alloc.cta_group::1.sync.aligned.shared::cta.b32 [%0], %1;"
                 :: "r"(smem_dst), "r"(ncols) : "memory");
}
__device__ __forceinline__ void tmem_dealloc(uint32_t tmem, uint32_t ncols) {
    asm volatile("tcgen05.dealloc.cta_group::1.sync.aligned.b32 %0, %1;" :: "r"(tmem), "r"(ncols));
}
__device__ __forceinline__ void tmem_relinquish() {
    asm volatile("tcgen05.relinquish_alloc_permit.cta_group::1.sync.aligned;");
}
__device__ __forceinline__ void tcommit(uint32_t mbar) {
    asm volatile("tcgen05.commit.cta_group::1.mbarrier::arrive::one.shared::cluster.b64 [%0];"
                 :: "r"(mbar) : "memory");
}
__device__ __forceinline__ void tc_fence_after() {
    asm volatile("tcgen05.fence::after_thread_sync;" ::: "memory");
}
__device__ __forceinline__ void fence_async_smem() {
    asm volatile("fence.proxy.async.shared::cta;" ::: "memory");
}
__device__ __forceinline__ void mma_tf32(uint32_t d, uint64_t ad, uint64_t bd,
                                         uint32_t idesc, uint32_t accum) {
    asm volatile(
        "{\n\t.reg .pred p;\n\t"
        "setp.ne.u32 p, %4, 0;\n\t"
        "tcgen05.mma.cta_group::1.kind::tf32 [%0], %1, %2, %3, {%5, %5, %5, %5}, p;\n\t}"
        :: "r"(d), "l"(ad), "l"(bd), "r"(idesc), "r"(accum), "r"(0u) : "memory");
}
__device__ __forceinline__ void ldtm_x32(uint32_t* r, uint32_t ta) {
    asm volatile(
        "tcgen05.ld.sync.aligned.32x32b.x32.b32 "
        "{%0,%1,%2,%3,%4,%5,%6,%7,%8,%9,%10,%11,%12,%13,%14,%15,"
        "%16,%17,%18,%19,%20,%21,%22,%23,%24,%25,%26,%27,%28,%29,%30,%31}, [%32];"
        : "=r"(r[0]), "=r"(r[1]), "=r"(r[2]), "=r"(r[3]), "=r"(r[4]), "=r"(r[5]), "=r"(r[6]), "=r"(r[7]),
          "=r"(r[8]), "=r"(r[9]), "=r"(r[10]), "=r"(r[11]), "=r"(r[12]), "=r"(r[13]), "=r"(r[14]), "=r"(r[15]),
          "=r"(r[16]), "=r"(r[17]), "=r"(r[18]), "=r"(r[19]), "=r"(r[20]), "=r"(r[21]), "=r"(r[22]), "=r"(r[23]),
          "=r"(r[24]), "=r"(r[25]), "=r"(r[26]), "=r"(r[27]), "=r"(r[28]), "=r"(r[29]), "=r"(r[30]), "=r"(r[31])
        : "r"(ta));
}
#define LDTM_WAIT() asm volatile("tcgen05.wait::ld.sync.aligned;" ::: "memory")

// K-major SW128 descriptor (validated config): LBO=1, SBO=64, version=1
static constexpr uint64_t DESC_K =
    (2ULL << 61) | (1ULL << 46) | (64ULL << 32) | (1ULL << 16);
// idesc: known-good f16 idesc 0x8080490 (M=128,N=32,F32 acc, K-major both)
// with atype=btype=TF32(2) instead of BF16(1); NO TransB.
static constexpr uint32_t IDESC_TF32 = 0x8080910u;
#endif  // HAS_TCGEN05

// dynamic SMEM: header + 1KB align slack + 4 stages x (16KB A + 16KB B)
#define SM_TOTAL 133120

// ---------------- transpose + tf32-round pre-pass: Wt[n][k] = rn(W[k][n]) ----------------
__global__ __launch_bounds__(256)
void transpose_round_kernel(const float* __restrict__ W, float* __restrict__ Wt,
                            int K, int N)
{
    __shared__ float t[32][33];
    int kb = blockIdx.y * 32, nb = blockIdx.x * 32;
    int tx = threadIdx.x & 31, ty = threadIdx.x >> 5;   // 32 x 8
    #pragma unroll
    for (int i = 0; i < 32; i += 8)
        t[ty + i][tx] = tf32_rn(W[(size_t)(kb + ty + i) * N + nb + tx]);
    __syncthreads();
    #pragma unroll
    for (int i = 0; i < 32; i += 8)
        Wt[(size_t)(nb + ty + i) * K + kb + tx] = t[tx][ty + i];
}

// ---------------- RoI adaptive max pool (output tf32-rounded) ----------------
__global__ void roi_pool_kernel(const float* __restrict__ x,
                                const float* __restrict__ rois,
                                float* __restrict__ pool)
{
    int n = blockIdx.x;
    __shared__ int rs[7], re[7], cs[7], ce[7];
    if (threadIdx.x == 0) {
        int x1 = (int)(rois[n * 4 + 0] * 0.0625f);
        int y1 = (int)(rois[n * 4 + 1] * 0.0625f);
        int x2 = (int)(rois[n * 4 + 2] * 0.0625f);
        int y2 = (int)(rois[n * 4 + 3] * 0.0625f);
        int h = y2 - y1 + 1;
        int w = x2 - x1 + 1;
        #pragma unroll
        for (int p = 0; p < 7; p++) {
            rs[p] = y1 + (p * h) / 7;
            re[p] = y1 + ((p + 1) * h + 6) / 7;
            cs[p] = x1 + (p * w) / 7;
            ce[p] = x1 + ((p + 1) * w + 6) / 7;
        }
    }
    __syncthreads();

    for (int c = threadIdx.x; c < CCH; c += blockDim.x) {
        const float* f = x + (size_t)c * HF * WF;
        float* out = pool + (size_t)n * FCIN + c * 49;
        #pragma unroll
        for (int ph = 0; ph < 7; ph++) {
            #pragma unroll
            for (int pw = 0; pw < 7; pw++) {
                float m = -CUDART_INF_F;
                for (int y = rs[ph]; y < re[ph]; y++) {
                    const float* frow = f + y * WF;
                    for (int xx = cs[pw]; xx < ce[pw]; xx++)
                        m = fmaxf(m, frow[xx]);
                }
                out[ph * 7 + pw] = tf32_rn(m);
            }
        }
    }
}

// ---------------- GEMM: C[512,4096] = relu(A[512,K] @ Bt[4096,K]^T + bias) ----------------
// A: [M,K] row-major. Bt: [N,K] row-major (pre-transposed weights).
// sm_103a: tcgen05 tf32, BOTH operands K-major SW128 (validated layout).
template <bool RELU, bool ROUND_OUT>
__global__ __launch_bounds__(256, 1)
void gemm_kernel(int K,
                 const float* __restrict__ A,
                 const float* __restrict__ Bt,
                 const float* __restrict__ bias,
                 float* __restrict__ C)
{
    extern __shared__ char smem[];
    const int tid = threadIdx.x;
    const int m0 = blockIdx.y * 128;
    const int n0 = blockIdx.x * 128;

#if HAS_TCGEN05
    const uint32_t sbase = smem_u32(smem);
    const uint32_t ubase = (sbase + 64 + 1023) & ~1023u;  // tiles, 1KB aligned
    const int wid = tid >> 5, lid = tid & 31;
    const int nt = K >> 5;

    if (tid == 0) {
        #pragma unroll
        for (int s = 0; s < 4; s++) mbar_init(sbase + 16 + s * 8, 1);
    }
    if (wid == 0) {
        tmem_alloc(sbase, 128);
        tmem_relinquish();
    }
    __syncthreads();
    const uint32_t tmem = *(const volatile uint32_t*)smem;

    const float* Abase = A  + (size_t)m0 * K;
    const float* Bbase = Bt + (size_t)n0 * K;

    auto load_tile = [&](int kt, int s) {
        uint32_t dA = ubase + s * 16384;
        uint32_t dB = ubase + 65536 + s * 16384;
        const float* Ab = Abase + (size_t)kt * 32;
        const float* Bb = Bbase + (size_t)kt * 32;
        // each tile: 128 rows x 128 bytes (32 tf32), K-major, SW128 swizzle
        #pragma unroll
        for (int i = 0; i < 4; i++) {
            int idx = tid + i * 256;
            int row = idx >> 3, c = idx & 7;
            cpasync16(dA + SWZ(row * 128 + c * 16), Ab + (size_t)row * K + c * 4);
        }
        #pragma unroll
        for (int i = 0; i < 4; i++) {
            int idx = tid + i * 256;
            int row = idx >> 3, c = idx & 7;
            cpasync16(dB + SWZ(row * 128 + c * 16), Bb + (size_t)row * K + c * 4);
        }
    };

    for (int p = 0; p < 3; p++) { load_tile(p, p); CP_COMMIT(); }

    for (int kt = 0; kt < nt; kt++) {
        int pt = kt + 3, ps = pt & 3;
        if (kt > 0)   // stage ps last used by MMA group of tile kt-1
            mbar_wait(sbase + 16 + ps * 8, ((uint32_t)(kt - 1) >> 2) & 1);
        if (pt < nt) load_tile(pt, ps);
        CP_COMMIT();
        CP_WAIT3();                    // tile kt resident
        fence_async_smem();
        __syncthreads();

        if (tid == 0) {
            tc_fence_after();
            uint32_t aaddr = ubase + (kt & 3) * 16384;
            uint32_t baddr = ubase + 65536 + (kt & 3) * 16384;
            uint64_t ad  = DESC_K | ((aaddr >> 4) & 0x3FFF);
            uint64_t bd0 = DESC_K | ((baddr >> 4) & 0x3FFF);
            #pragma unroll
            for (int j = 0; j < 4; j++) {           // 4 N-chunks of 32 rows of B
                uint64_t bd = bd0 + j * 256;        // +32 rows x 128B = 4096B
                #pragma unroll
                for (int ks = 0; ks < 4; ks++)      // 4 K-steps of 8 (32B each)
                    mma_tf32(tmem + j * 32, ad + ks * 2, bd + ks * 2,
                             IDESC_TF32, (kt > 0 || ks > 0) ? 1u : 0u);
            }
            tcommit(sbase + 16 + (kt & 3) * 8);
        }
    }

    {
        int lk = nt - 1;
        mbar_wait(sbase + 16 + (lk & 3) * 8, ((uint32_t)lk >> 2) & 1);
    }
    tc_fence_after();
    if (wid < 4) {
        #pragma unroll
        for (int cb = 0; cb < 4; cb++) {
            uint32_t r[32];
            ldtm_x32(r, tmem + cb * 32);
            LDTM_WAIT();
            int m = m0 + wid * 32 + lid;
            float* Crow = C + (size_t)m * GN + n0 + cb * 32;
            const float* brow = bias + n0 + cb * 32;
            #pragma unroll
            for (int i = 0; i < 32; i++) {
                float v = __uint_as_float(r[i]) + brow[i];
                if (RELU) v = fmaxf(v, 0.f);
                if (ROUND_OUT) v = tf32_rn(v);
                Crow[i] = v;
            }
        }
    }
    __syncthreads();
    if (wid == 0) tmem_dealloc(tmem, 128);

#else  // ---------------- fp32 fallback (B pre-transposed: Bt[n][k]) ----------------
    float* As = (float*)smem;                 // [16][132] transposed A tile
    float* Bs = (float*)smem + 16 * 132;      // [128][18] Bt tile rows=n
    const int tx = tid & 15;    // n (x8)
    const int ty = tid >> 4;    // m (x8)

    float acc[8][8];
    #pragma unroll
    for (int i = 0; i < 8; i++)
        #pragma unroll
        for (int j = 0; j < 8; j++) acc[i][j] = 0.f;

    const float* Ablk = A  + (size_t)m0 * K;
    const float* Bblk = Bt + (size_t)n0 * K;

    for (int k0 = 0; k0 < K; k0 += 16) {
        #pragma unroll
        for (int t = 0; t < 2; t++) {         // A: 128 rows x 16k = 512 float4
            int idx = tid + t * 256;
            int row = idx >> 2;
            int kc  = (idx & 3) * 4;
            float4 v = *(const float4*)(Ablk + (size_t)row * K + k0 + kc);
            As[(kc + 0) * 132 + row] = v.x;
            As[(kc + 1) * 132 + row] = v.y;
            As[(kc + 2) * 132 + row] = v.z;
            As[(kc + 3) * 132 + row] = v.w;
        }
        #pragma unroll
        for (int t = 0; t < 2; t++) {         // Bt: 128 rows x 16k = 512 float4
            int idx = tid + t * 256;
            int row = idx >> 2;
            int kc  = (idx & 3) * 4;
            float4 v = *(const float4*)(Bblk + (size_t)row * K + k0 + kc);
            Bs[row * 18 + kc + 0] = v.x;
            Bs[row * 18 + kc + 1] = v.y;
            Bs[row * 18 + kc + 2] = v.z;
            Bs[row * 18 + kc + 3] = v.w;
        }
        __syncthreads();

        #pragma unroll
        for (int k = 0; k < 16; k++) {
            float a[8], b[8];
            *(float4*)&a[0] = *(const float4*)&As[k * 132 + ty * 8 + 0];
            *(float4*)&a[4] = *(const float4*)&As[k * 132 + ty * 8 + 4];
            #pragma unroll
            for (int j = 0; j < 8; j++) b[j] = Bs[(tx * 8 + j) * 18 + k];
            #pragma unroll
            for (int i = 0; i < 8; i++)
                #pragma unroll
                for (int j = 0; j < 8; j++)
                    acc[i][j] = fmaf(a[i], b[j], acc[i][j]);
        }
        __syncthreads();
    }

    #pragma unroll
    for (int i = 0; i < 8; i++) {
        int m = m0 + ty * 8 + i;
        #pragma unroll
        for (int j = 0; j < 8; j++) {
            int n = n0 + tx * 8 + j;
            float v = acc[i][j] + bias[n];
            if (RELU) v = fmaxf(v, 0.f);
            if (ROUND_OUT) v = tf32_rn(v);
            C[(size_t)m * GN + n] = v;
        }
    }
#endif
}

// ---------------- head weight transpose ----------------
__global__ void transpose_head_kernel(const float* __restrict__ Wl,
                                      const float* __restrict__ Ws,
                                      float* __restrict__ Wt)
{
    int idx = blockIdx.x * 256 + threadIdx.x;
    if (idx >= NHEAD * FCD) return;
    int o = idx >> 12, k = idx & 4095;
    Wt[idx] = (o < NLOC) ? Wl[(size_t)k * NLOC + o] : Ws[(size_t)k * NSC + (o - NLOC)];
}

// ---------------- head: 8 rois/block, warp-per-output ----------------
__global__ __launch_bounds__(256, 1)
void head_kernel(const float* __restrict__ fc,
                 const float* __restrict__ Wt,
                 const float* __restrict__ bl, const float* __restrict__ bs,
                 float* __restrict__ out_loc, float* __restrict__ out_sc)
{
    extern __shared__ float sfc[];   // 8 x 4096
    int b0 = blockIdx.x * 8;
    int tid = threadIdx.x;
    for (int r = 0; r < 8; r++)
        for (int k = tid; k < FCD; k += 256)
            sfc[r * FCD + k] = fc[(size_t)(b0 + r) * FCD + k];
    __syncthreads();

    int w = tid >> 5, lane = tid & 31;
    for (int o = w; o < NHEAD; o += 8) {
        const float4* wp = (const float4*)(Wt + (size_t)o * FCD);
        float acc[8];
        #pragma unroll
        for (int r = 0; r < 8; r++) acc[r] = 0.f;
        for (int k4 = lane; k4 < FCD / 4; k4 += 32) {
            float4 wv = wp[k4];
            #pragma unroll
            for (int r = 0; r < 8; r++) {
                float4 f = *(const float4*)&sfc[r * FCD + k4 * 4];
                acc[r] += wv.x * f.x + wv.y * f.y + wv.z * f.z + wv.w * f.w;
            }
        }
        #pragma unroll
        for (int off = 16; off; off >>= 1)
            #pragma unroll
            for (int r = 0; r < 8; r++)
                acc[r] += __shfl_xor_sync(0xFFFFFFFFu, acc[r], off);
        if (lane == 0) {
            if (o < NLOC) {
                float b = bl[o];
                #pragma unroll
                for (int r = 0; r < 8; r++) out_loc[(size_t)(b0 + r) * NLOC + o] = acc[r] + b;
            } else {
                float b = bs[o - NLOC];
                #pragma unroll
                for (int r = 0; r < 8; r++) out_sc[(size_t)(b0 + r) * NSC + (o - NLOC)] = acc[r] + b;
            }
        }
    }
}

// ---------------- launch ----------------
extern "C" void kernel_launch(void* const* d_in, const int* in_sizes, int n_in,
                              void* d_out, int out_size)
{
    const float* x      = (const float*)d_in[0];
    const float* rois   = (const float*)d_in[1];
    const float* W1     = (const float*)d_in[2];
    const float* b1     = (const float*)d_in[3];
    const float* W2     = (const float*)d_in[4];
    const float* b2     = (const float*)d_in[5];
    const float* W_loc  = (const float*)d_in[6];
    const float* b_loc  = (const float*)d_in[7];
    const float* W_sc   = (const float*)d_in[8];
    const float* b_sc   = (const float*)d_in[9];
    float* out = (float*)d_out;

    float *p_pool, *p_fc1, *p_fc2, *p_wt, *p_w1t, *p_w2t;
    cudaGetSymbolAddress((void**)&p_pool, g_pool);
    cudaGetSymbolAddress((void**)&p_fc1,  g_fc1);
    cudaGetSymbolAddress((void**)&p_fc2,  g_fc2);
    cudaGetSymbolAddress((void**)&p_wt,   g_wt);
    cudaGetSymbolAddress((void**)&p_w1t,  g_w1t);
    cudaGetSymbolAddress((void**)&p_w2t,  g_w2t);

    cudaFuncSetAttribute(gemm_kernel<true, true>,
                         cudaFuncAttributeMaxDynamicSharedMemorySize, SM_TOTAL);
    cudaFuncSetAttribute(gemm_kernel<true, false>,
                         cudaFuncAttributeMaxDynamicSharedMemorySize, SM_TOTAL);
    cudaFuncSetAttribute(head_kernel,
                         cudaFuncAttributeMaxDynamicSharedMemorySize, 8 * FCD * 4);

    // 0) transpose + RN-round weights: W[K,N] -> Wt[N,K] (tf32 values)
    {
        dim3 gt1(FCD / 32, FCIN / 32);
        transpose_round_kernel<<<gt1, 256>>>(W1, p_w1t, FCIN, FCD);
        dim3 gt2(FCD / 32, FCD / 32);
        transpose_round_kernel<<<gt2, 256>>>(W2, p_w2t, FCD, FCD);
    }

    // 1) RoI adaptive max pool (tf32-rounded output)
    roi_pool_kernel<<<NROI, 256>>>(x, rois, p_pool);

    // 2) fc1 = relu(pool @ W1 + b1), output tf32-rounded
    dim3 g(GN / 128, NROI / 128);
    gemm_kernel<true, true><<<g, 256, SM_TOTAL>>>(FCIN, p_pool, p_w1t, b1, p_fc1);

    // 3) fc2 = relu(fc1 @ W2 + b2)
    gemm_kernel<true, false><<<g, 256, SM_TOTAL>>>(FCD, p_fc1, p_w2t, b2, p_fc2);

    // 4) head
    transpose_head_kernel<<<(NHEAD * FCD) / 256, 256>>>(W_loc, W_sc, p_wt);
    head_kernel<<<NROI / 8, 256, 8 * FCD * 4>>>(p_fc2, p_wt, b_loc, b_sc,
                                                out, out + (size_t)NROI * NLOC);
}

// round 5
// speedup vs baseline: 4.8199x; 1.3959x over previous
#include <cuda_runtime.h>
#include <cstdint>
#include <math_constants.h>

// ---------------- problem constants ----------------
#define CCH 512
#define HF 50
#define WF 75
#define NROI 512
#define FCIN 25088
#define FCD 4096
#define GN 4096
#define NLOC 84
#define NSC 21
#define NHEAD 105

#if defined(__CUDA_ARCH__) && defined(__CUDA_ARCH_FEAT_SM103_ALL)
#define HAS_TCGEN05 1
#else
#define HAS_TCGEN05 0
#endif

// ---------------- device scratch ----------------
__device__ float g_pool[(size_t)NROI * FCIN];    // 51.4 MB (tf32-rounded)
__device__ float g_fc1[(size_t)NROI * FCD];      // 8 MB (tf32-rounded)
__device__ float g_fc2[(size_t)NROI * FCD];      // 8 MB
__device__ float g_w1t[(size_t)FCIN * FCD];      // 411 MB W1^T [N,K] tf32
__device__ float g_w2t[(size_t)FCD * FCD];       // 67 MB  W2^T [N,K] tf32
__device__ float g_wt[(size_t)NHEAD * FCD];      // head weights transposed

// ---------------- common helpers ----------------
__device__ __forceinline__ float tf32_rn(float x) {
    float r;
    asm("cvt.rna.tf32.f32 %0, %1;" : "=f"(r) : "f"(x));
    return r;
}
__device__ __forceinline__ uint32_t smem_u32(const void* p) {
    uint32_t a;
    asm("{ .reg .u64 t; cvta.to.shared.u64 t, %1; cvt.u32.u64 %0, t; }" : "=r"(a) : "l"(p));
    return a;
}
__device__ __forceinline__ void cpasync16(uint32_t dst, const void* src) {
    asm volatile("cp.async.cg.shared.global [%0], [%1], 16;" :: "r"(dst), "l"(src));
}
#define SWZ(x) ((x) ^ (((x) >> 3) & 0x70))

#if HAS_TCGEN05
// ---------------- tcgen05 helpers (sm_103a pass only) ----------------
__device__ __forceinline__ void mbar_init(uint32_t mbar, uint32_t cnt) {
    asm volatile("mbarrier.init.shared.b64 [%0], %1;" :: "r"(mbar), "r"(cnt) : "memory");
}
__device__ __forceinline__ void mbar_wait(uint32_t mbar, uint32_t parity) {
    asm volatile(
        "{\n\t.reg .pred P;\n"
        "LW_%=:\n\t"
        "mbarrier.try_wait.parity.acquire.cta.shared::cta.b64 P, [%0], %1, 0x989680;\n\t"
        "@P bra.uni LD_%=;\n\t"
        "bra.uni LW_%=;\n"
        "LD_%=:\n\t}"
        :: "r"(mbar), "r"(parity) : "memory");
}
__device__ __forceinline__ void cpasync_arrive(uint32_t mbar) {
    asm volatile("cp.async.mbarrier.arrive.noinc.shared.b64 [%0];" :: "r"(mbar) : "memory");
}
__device__ __forceinline__ void tmem_alloc(uint32_t smem_dst, uint32_t ncols) {
    asm volatile("tcgen05.alloc.cta_group::1.sync.aligned.shared::cta.b32 [%0], %1;"
                 :: "r"(smem_dst), "r"(ncols) : "memory");
}
__device__ __forceinline__ void tmem_dealloc(uint32_t tmem, uint32_t ncols) {
    asm volatile("tcgen05.dealloc.cta_group::1.sync.aligned.b32 %0, %1;" :: "r"(tmem), "r"(ncols));
}
__device__ __forceinline__ void tmem_relinquish() {
    asm volatile("tcgen05.relinquish_alloc_permit.cta_group::1.sync.aligned;");
}
__device__ __forceinline__ void tcommit(uint32_t mbar) {
    asm volatile("tcgen05.commit.cta_group::1.mbarrier::arrive::one.shared::cluster.b64 [%0];"
                 :: "r"(mbar) : "memory");
}
__device__ __forceinline__ void tc_fence_after() {
    asm volatile("tcgen05.fence::after_thread_sync;" ::: "memory");
}
__device__ __forceinline__ void fence_async_smem() {
    asm volatile("fence.proxy.async.shared::cta;" ::: "memory");
}
__device__ __forceinline__ void mma_tf32(uint32_t d, uint64_t ad, uint64_t bd,
                                         uint32_t idesc, uint32_t accum) {
    asm volatile(
        "{\n\t.reg .pred p;\n\t"
        "setp.ne.u32 p, %4, 0;\n\t"
        "tcgen05.mma.cta_group::1.kind::tf32 [%0], %1, %2, %3, {%5, %5, %5, %5}, p;\n\t}"
        :: "r"(d), "l"(ad), "l"(bd), "r"(idesc), "r"(accum), "r"(0u) : "memory");
}
__device__ __forceinline__ void ldtm_x32(uint32_t* r, uint32_t ta) {
    asm volatile(
        "tcgen05.ld.sync.aligned.32x32b.x32.b32 "
        "{%0,%1,%2,%3,%4,%5,%6,%7,%8,%9,%10,%11,%12,%13,%14,%15,"
        "%16,%17,%18,%19,%20,%21,%22,%23,%24,%25,%26,%27,%28,%29,%30,%31}, [%32];"
        : "=r"(r[0]), "=r"(r[1]), "=r"(r[2]), "=r"(r[3]), "=r"(r[4]), "=r"(r[5]), "=r"(r[6]), "=r"(r[7]),
          "=r"(r[8]), "=r"(r[9]), "=r"(r[10]), "=r"(r[11]), "=r"(r[12]), "=r"(r[13]), "=r"(r[14]), "=r"(r[15]),
          "=r"(r[16]), "=r"(r[17]), "=r"(r[18]), "=r"(r[19]), "=r"(r[20]), "=r"(r[21]), "=r"(r[22]), "=r"(r[23]),
          "=r"(r[24]), "=r"(r[25]), "=r"(r[26]), "=r"(r[27]), "=r"(r[28]), "=r"(r[29]), "=r"(r[30]), "=r"(r[31])
        : "r"(ta));
}
#define LDTM_WAIT() asm volatile("tcgen05.wait::ld.sync.aligned;" ::: "memory")

// K-major SW128 descriptor (validated): LBO=1, SBO=64, version=1
static constexpr uint64_t DESC_K =
    (2ULL << 61) | (1ULL << 46) | (64ULL << 32) | (1ULL << 16);
// idesc: F32 acc, tf32 a/b, K-major both, M=128, N=128 (one dispatch covers B tile)
static constexpr uint32_t IDESC_TF32_N128 = 0x8200910u;
#endif  // HAS_TCGEN05

#define NSTAGE 5
// dyn smem: 128B header (tmemptr + mbars) + align + 5 x 32KB stages
#define SM_TOTAL 166912

// ---------------- transpose + tf32-round pre-pass: Wt[n][k] = rn(W[k][n]) ----------------
__global__ __launch_bounds__(256)
void transpose_round_kernel(const float* __restrict__ W, float* __restrict__ Wt,
                            int K, int N)
{
    __shared__ float t[32][33];
    int kb = blockIdx.y * 32, nb = blockIdx.x * 32;
    int tx = threadIdx.x & 31, ty = threadIdx.x >> 5;
    #pragma unroll
    for (int i = 0; i < 32; i += 8)
        t[ty + i][tx] = tf32_rn(W[(size_t)(kb + ty + i) * N + nb + tx]);
    __syncthreads();
    #pragma unroll
    for (int i = 0; i < 32; i += 8)
        Wt[(size_t)(nb + ty + i) * K + kb + tx] = t[tx][ty + i];
}

// ---------------- RoI adaptive max pool ----------------
__global__ void roi_pool_kernel(const float* __restrict__ x,
                                const float* __restrict__ rois,
                                float* __restrict__ pool)
{
    int n = blockIdx.x;
    __shared__ int rs[7], re[7], cs[7], ce[7];
    if (threadIdx.x == 0) {
        int x1 = (int)(rois[n * 4 + 0] * 0.0625f);
        int y1 = (int)(rois[n * 4 + 1] * 0.0625f);
        int x2 = (int)(rois[n * 4 + 2] * 0.0625f);
        int y2 = (int)(rois[n * 4 + 3] * 0.0625f);
        int h = y2 - y1 + 1;
        int w = x2 - x1 + 1;
        #pragma unroll
        for (int p = 0; p < 7; p++) {
            rs[p] = y1 + (p * h) / 7;
            re[p] = y1 + ((p + 1) * h + 6) / 7;
            cs[p] = x1 + (p * w) / 7;
            ce[p] = x1 + ((p + 1) * w + 6) / 7;
        }
    }
    __syncthreads();

    for (int c = threadIdx.x; c < CCH; c += blockDim.x) {
        const float* f = x + (size_t)c * HF * WF;
        float* out = pool + (size_t)n * FCIN + c * 49;
        #pragma unroll
        for (int ph = 0; ph < 7; ph++) {
            #pragma unroll
            for (int pw = 0; pw < 7; pw++) {
                float m = -CUDART_INF_F;
                for (int y = rs[ph]; y < re[ph]; y++) {
                    const float* frow = f + y * WF;
                    for (int xx = cs[pw]; xx < ce[pw]; xx++)
                        m = fmaxf(m, frow[xx]);
                }
                out[ph * 7 + pw] = tf32_rn(m);
            }
        }
    }
}

// ---------------- warp-specialized tcgen05 tf32 GEMM ----------------
// C[512,4096] = relu(A[512,K] @ Bt[4096,K]^T + bias). A,Bt row-major, K-major tiles.
// warps 0-3: cp.async producers; tid 128: MMA issuer; warps 4-7: epilogue.
template <bool RELU, bool ROUND_OUT>
__global__ __launch_bounds__(256, 1)
void gemm_kernel(int K,
                 const float* __restrict__ A,
                 const float* __restrict__ Bt,
                 const float* __restrict__ bias,
                 float* __restrict__ C)
{
    extern __shared__ char smem[];
    const int tid = threadIdx.x;
    const int m0 = blockIdx.y * 128;
    const int n0 = blockIdx.x * 128;

#if HAS_TCGEN05
    const uint32_t sbase = smem_u32(smem);
    const uint32_t ubase = (sbase + 128 + 1023) & ~1023u;
    const int wid = tid >> 5, lid = tid & 31;
    const int nt = K >> 5;
    // mbar layout: full[s]=sbase+16+8s, empty[s]=sbase+56+8s, done=sbase+96
    const uint32_t mb_full  = sbase + 16;
    const uint32_t mb_empty = sbase + 56;
    const uint32_t mb_done  = sbase + 96;

    if (tid == 0) {
        #pragma unroll
        for (int s = 0; s < NSTAGE; s++) {
            mbar_init(mb_full + s * 8, 128);   // 128 producer threads
            mbar_init(mb_empty + s * 8, 1);    // one MMA commit
        }
        mbar_init(mb_done, 1);
    }
    if (wid == 0) {
        tmem_alloc(sbase, 128);
        tmem_relinquish();
    }
    __syncthreads();
    const uint32_t tmem = *(const volatile uint32_t*)smem;

    const float* Abase = A  + (size_t)m0 * K;
    const float* Bbase = Bt + (size_t)n0 * K;

    if (wid < 4) {
        // ---------------- producers ----------------
        for (int t = 0; t < nt; t++) {
            int s = t - (t / NSTAGE) * NSTAGE;
            if (t >= NSTAGE)
                mbar_wait(mb_empty + s * 8, (t / NSTAGE - 1) & 1);
            uint32_t dA = ubase + s * 32768;
            uint32_t dB = dA + 16384;
            const float* Ab = Abase + (size_t)t * 32;
            const float* Bb = Bbase + (size_t)t * 32;
            #pragma unroll
            for (int i = 0; i < 8; i++) {
                int idx = tid + i * 128;
                int row = idx >> 3, c = idx & 7;
                cpasync16(dA + SWZ(row * 128 + c * 16), Ab + (size_t)row * K + c * 4);
            }
            #pragma unroll
            for (int i = 0; i < 8; i++) {
                int idx = tid + i * 128;
                int row = idx >> 3, c = idx & 7;
                cpasync16(dB + SWZ(row * 128 + c * 16), Bb + (size_t)row * K + c * 4);
            }
            cpasync_arrive(mb_full + s * 8);
        }
    } else if (tid == 128) {
        // ---------------- MMA issuer ----------------
        for (int t = 0; t < nt; t++) {
            int s = t - (t / NSTAGE) * NSTAGE;
            mbar_wait(mb_full + s * 8, (t / NSTAGE) & 1);
            fence_async_smem();
            tc_fence_after();
            uint32_t aaddr = ubase + s * 32768;
            uint32_t baddr = aaddr + 16384;
            uint64_t ad = DESC_K | ((aaddr >> 4) & 0x3FFF);
            uint64_t bd = DESC_K | ((baddr >> 4) & 0x3FFF);
            #pragma unroll
            for (int ks = 0; ks < 4; ks++)     // 4 K-steps of 8 (32B each)
                mma_tf32(tmem, ad + ks * 2, bd + ks * 2,
                         IDESC_TF32_N128, (t > 0 || ks > 0) ? 1u : 0u);
            tcommit(mb_empty + s * 8);
        }
        tcommit(mb_done);
    }

    // ---------------- epilogue ----------------
    mbar_wait(mb_done, 0);
    __syncthreads();
    tc_fence_after();
    if (wid >= 4) {
        int m = m0 + (wid & 3) * 32 + lid;
        #pragma unroll
        for (int cb = 0; cb < 4; cb++) {
            uint32_t r[32];
            ldtm_x32(r, tmem + cb * 32);
            LDTM_WAIT();
            float* Crow = C + (size_t)m * GN + n0 + cb * 32;
            const float* brow = bias + n0 + cb * 32;
            #pragma unroll
            for (int i = 0; i < 32; i++) {
                float v = __uint_as_float(r[i]) + brow[i];
                if (RELU) v = fmaxf(v, 0.f);
                if (ROUND_OUT) v = tf32_rn(v);
                Crow[i] = v;
            }
        }
    }
    __syncthreads();
    if (wid == 0) tmem_dealloc(tmem, 128);

#else  // ---------------- fp32 fallback (non-103a pass) ----------------
    float* As = (float*)smem;                 // [16][132]
    float* Bs = (float*)smem + 16 * 132;      // [128][18]
    const int tx = tid & 15;
    const int ty = tid >> 4;

    float acc[8][8];
    #pragma unroll
    for (int i = 0; i < 8; i++)
        #pragma unroll
        for (int j = 0; j < 8; j++) acc[i][j] = 0.f;

    const float* Ablk = A  + (size_t)m0 * K;
    const float* Bblk = Bt + (size_t)n0 * K;

    for (int k0 = 0; k0 < K; k0 += 16) {
        #pragma unroll
        for (int t = 0; t < 2; t++) {
            int idx = tid + t * 256;
            int row = idx >> 2;
            int kc  = (idx & 3) * 4;
            float4 v = *(const float4*)(Ablk + (size_t)row * K + k0 + kc);
            As[(kc + 0) * 132 + row] = v.x;
            As[(kc + 1) * 132 + row] = v.y;
            As[(kc + 2) * 132 + row] = v.z;
            As[(kc + 3) * 132 + row] = v.w;
        }
        #pragma unroll
        for (int t = 0; t < 2; t++) {
            int idx = tid + t * 256;
            int row = idx >> 2;
            int kc  = (idx & 3) * 4;
            float4 v = *(const float4*)(Bblk + (size_t)row * K + k0 + kc);
            Bs[row * 18 + kc + 0] = v.x;
            Bs[row * 18 + kc + 1] = v.y;
            Bs[row * 18 + kc + 2] = v.z;
            Bs[row * 18 + kc + 3] = v.w;
        }
        __syncthreads();

        #pragma unroll
        for (int k = 0; k < 16; k++) {
            float a[8], b[8];
            *(float4*)&a[0] = *(const float4*)&As[k * 132 + ty * 8 + 0];
            *(float4*)&a[4] = *(const float4*)&As[k * 132 + ty * 8 + 4];
            #pragma unroll
            for (int j = 0; j < 8; j++) b[j] = Bs[(tx * 8 + j) * 18 + k];
            #pragma unroll
            for (int i = 0; i < 8; i++)
                #pragma unroll
                for (int j = 0; j < 8; j++)
                    acc[i][j] = fmaf(a[i], b[j], acc[i][j]);
        }
        __syncthreads();
    }

    #pragma unroll
    for (int i = 0; i < 8; i++) {
        int m = m0 + ty * 8 + i;
        #pragma unroll
        for (int j = 0; j < 8; j++) {
            int n = n0 + tx * 8 + j;
            float v = acc[i][j] + bias[n];
            if (RELU) v = fmaxf(v, 0.f);
            if (ROUND_OUT) v = tf32_rn(v);
            C[(size_t)m * GN + n] = v;
        }
    }
#endif
}

// ---------------- head weight transpose ----------------
__global__ void transpose_head_kernel(const float* __restrict__ Wl,
                                      const float* __restrict__ Ws,
                                      float* __restrict__ Wt)
{
    int idx = blockIdx.x * 256 + threadIdx.x;
    if (idx >= NHEAD * FCD) return;
    int o = idx >> 12, k = idx & 4095;
    Wt[idx] = (o < NLOC) ? Wl[(size_t)k * NLOC + o] : Ws[(size_t)k * NSC + (o - NLOC)];
}

// ---------------- head: 8 rois/block, warp-per-output ----------------
__global__ __launch_bounds__(256, 1)
void head_kernel(const float* __restrict__ fc,
                 const float* __restrict__ Wt,
                 const float* __restrict__ bl, const float* __restrict__ bs,
                 float* __restrict__ out_loc, float* __restrict__ out_sc)
{
    extern __shared__ float sfc[];   // 8 x 4096
    int b0 = blockIdx.x * 8;
    int tid = threadIdx.x;
    for (int r = 0; r < 8; r++)
        for (int k = tid; k < FCD; k += 256)
            sfc[r * FCD + k] = fc[(size_t)(b0 + r) * FCD + k];
    __syncthreads();

    int w = tid >> 5, lane = tid & 31;
    for (int o = w; o < NHEAD; o += 8) {
        const float4* wp = (const float4*)(Wt + (size_t)o * FCD);
        float acc[8];
        #pragma unroll
        for (int r = 0; r < 8; r++) acc[r] = 0.f;
        for (int k4 = lane; k4 < FCD / 4; k4 += 32) {
            float4 wv = wp[k4];
            #pragma unroll
            for (int r = 0; r < 8; r++) {
                float4 f = *(const float4*)&sfc[r * FCD + k4 * 4];
                acc[r] += wv.x * f.x + wv.y * f.y + wv.z * f.z + wv.w * f.w;
            }
        }
        #pragma unroll
        for (int off = 16; off; off >>= 1)
            #pragma unroll
            for (int r = 0; r < 8; r++)
                acc[r] += __shfl_xor_sync(0xFFFFFFFFu, acc[r], off);
        if (lane == 0) {
            if (o < NLOC) {
                float b = bl[o];
                #pragma unroll
                for (int r = 0; r < 8; r++) out_loc[(size_t)(b0 + r) * NLOC + o] = acc[r] + b;
            } else {
                float b = bs[o - NLOC];
                #pragma unroll
                for (int r = 0; r < 8; r++) out_sc[(size_t)(b0 + r) * NSC + (o - NLOC)] = acc[r] + b;
            }
        }
    }
}

// ---------------- launch ----------------
extern "C" void kernel_launch(void* const* d_in, const int* in_sizes, int n_in,
                              void* d_out, int out_size)
{
    const float* x      = (const float*)d_in[0];
    const float* rois   = (const float*)d_in[1];
    const float* W1     = (const float*)d_in[2];
    const float* b1     = (const float*)d_in[3];
    const float* W2     = (const float*)d_in[4];
    const float* b2     = (const float*)d_in[5];
    const float* W_loc  = (const float*)d_in[6];
    const float* b_loc  = (const float*)d_in[7];
    const float* W_sc   = (const float*)d_in[8];
    const float* b_sc   = (const float*)d_in[9];
    float* out = (float*)d_out;

    float *p_pool, *p_fc1, *p_fc2, *p_wt, *p_w1t, *p_w2t;
    cudaGetSymbolAddress((void**)&p_pool, g_pool);
    cudaGetSymbolAddress((void**)&p_fc1,  g_fc1);
    cudaGetSymbolAddress((void**)&p_fc2,  g_fc2);
    cudaGetSymbolAddress((void**)&p_wt,   g_wt);
    cudaGetSymbolAddress((void**)&p_w1t,  g_w1t);
    cudaGetSymbolAddress((void**)&p_w2t,  g_w2t);

    cudaFuncSetAttribute(gemm_kernel<true, true>,
                         cudaFuncAttributeMaxDynamicSharedMemorySize, SM_TOTAL);
    cudaFuncSetAttribute(gemm_kernel<true, false>,
                         cudaFuncAttributeMaxDynamicSharedMemorySize, SM_TOTAL);
    cudaFuncSetAttribute(head_kernel,
                         cudaFuncAttributeMaxDynamicSharedMemorySize, 8 * FCD * 4);

    // 0) transpose + RN-round weights
    {
        dim3 gt1(FCD / 32, FCIN / 32);
        transpose_round_kernel<<<gt1, 256>>>(W1, p_w1t, FCIN, FCD);
        dim3 gt2(FCD / 32, FCD / 32);
        transpose_round_kernel<<<gt2, 256>>>(W2, p_w2t, FCD, FCD);
    }

    // 1) RoI adaptive max pool
    roi_pool_kernel<<<NROI, 256>>>(x, rois, p_pool);

    // 2) fc1 = relu(pool @ W1 + b1)
    dim3 g(GN / 128, NROI / 128);
    gemm_kernel<true, true><<<g, 256, SM_TOTAL>>>(FCIN, p_pool, p_w1t, b1, p_fc1);

    // 3) fc2 = relu(fc1 @ W2 + b2)
    gemm_kernel<true, false><<<g, 256, SM_TOTAL>>>(FCD, p_fc1, p_w2t, b2, p_fc2);

    // 4) head
    transpose_head_kernel<<<(NHEAD * FCD) / 256, 256>>>(W_loc, W_sc, p_wt);
    head_kernel<<<NROI / 8, 256, 8 * FCD * 4>>>(p_fc2, p_wt, b_loc, b_sc,
                                                out, out + (size_t)NROI * NLOC);
}